// round 11
// baseline (speedup 1.0000x reference)
#include <cuda_runtime.h>
#include <math.h>
#include <float.h>

#define Hh   1024
#define Ww   1024
#define CSc  62      // (1024-900)/2
#define OFFc 72      // MS + CS
#define TWc  880     // template window
#define Sc   21      // 2*MS+1
#define MSc  10
#define EPSc 1e-8f

#define ND3 968      // kernel D blocks (22 row tiles x 44 col tiles of 40x20)

// ---------------- scratch (no allocation allowed) ----------------
__device__ float g_tb[ND3], g_tbq[ND3];       // per-block template sum / sumsq
__device__ float g_part[20 * 900];            // 45-row chunk partial sums
__device__ float g_partq[20 * 900];
__device__ float g_colx[21 * 900];            // column sliding sums of Xc
__device__ float g_colq[21 * 900];
__device__ float g_corr[441 * ND3];           // lag-major correlation partials
__device__ float g_sum[441];                  // reduced correlation
__device__ float g_xy[2];                     // xs, ys

// ---------------- helpers ----------------
__device__ __forceinline__ void blockReduce2(float& s, float& q, float* sh) {
    int lane = threadIdx.x & 31, w = threadIdx.x >> 5;
    for (int o = 16; o > 0; o >>= 1) {
        s += __shfl_down_sync(0xffffffffu, s, o);
        q += __shfl_down_sync(0xffffffffu, q, o);
    }
    if (lane == 0) { sh[w] = s; sh[32 + w] = q; }
    __syncthreads();
    int nw = (blockDim.x + 31) >> 5;
    if (w == 0) {
        s = (lane < nw) ? sh[lane] : 0.f;
        q = (lane < nw) ? sh[32 + lane] : 0.f;
        for (int o = 16; o > 0; o >>= 1) {
            s += __shfl_down_sync(0xffffffffu, s, o);
            q += __shfl_down_sync(0xffffffffu, q, o);
        }
    }
    __syncthreads();
}

// ---------------- B1: per-column 45-row chunk partial sums ---------------
__global__ void kB1(const float* __restrict__ X) {
    int c = blockIdx.x * 128 + threadIdx.x;
    if (c >= 900) return;
    int r0 = blockIdx.y * 45;
    const float* p = X + (size_t)(CSc + r0) * Ww + CSc + c;
    float s = 0.f, q = 0.f;
#pragma unroll 5
    for (int r = 0; r < 45; r++) { float v = p[(size_t)r * Ww]; s += v; q = fmaf(v, v, q); }
    g_part[blockIdx.y * 900 + c] = s;
    g_partq[blockIdx.y * 900 + c] = q;
}

// ---------------- B2: total - head - tail  -> 21 sliding column sums -----
__global__ void kB2(const float* __restrict__ X) {
    int c = blockIdx.x * 256 + threadIdx.x;
    if (c >= 900) return;
    float s = 0.f, q = 0.f;
#pragma unroll
    for (int k = 0; k < 20; k++) { s += g_part[k * 900 + c]; q += g_partq[k * 900 + c]; }
    const float* p = X + (size_t)CSc * Ww + CSc + c;
    float ts = 0.f, tq = 0.f;
#pragma unroll
    for (int k = 0; k < 20; k++) {
        float w = p[(size_t)(880 + k) * Ww]; ts += w; tq = fmaf(w, w, tq);
    }
    float hp = 0.f, hq = 0.f;
#pragma unroll
    for (int i = 0; i < 21; i++) {
        g_colx[i * 900 + c] = s - hp - ts;
        g_colq[i * 900 + c] = q - hq - tq;
        if (i < 20) {
            float v = p[(size_t)i * Ww];          hp += v; hq = fmaf(v, v, hq);
            float w = p[(size_t)(880 + i) * Ww];  ts -= w; tq -= w * w;
        }
    }
}

// ---------------- D: correlation, 40x20 tiles, register-resident row -----
// 168 threads = 21 row-lags x 8 reduction slices. 40-wide image row window
// in registers (fits 64-96 regs); inner loop = 1 LDS + 21 indep FFMA.
// Also computes per-block template sum/sumsq (replaces old kA).
__global__ void __launch_bounds__(168, 4) kD(const float* __restrict__ X,
                                             const float* __restrict__ T) {
    __shared__ float Xs[60 * 41];    // 60 rows x 40 cols, pitch 41 (Δrow -> +9 banks)
    __shared__ float Ts[40 * 21];    // 40 rows x 20 cols, pitch 21 (Δrow -> distinct banks)
    __shared__ float sh[64];
    int b = blockIdx.x;
    int bi = b / 44, bj = b % 44;    // 22 x 44 tiles: template tile 40 rows x 20 cols
    int bu0 = bi * 40, bv0 = bj * 20;
    int tid = threadIdx.x;

    const float* xg = X + (size_t)(CSc + bu0) * Ww + (CSc + bv0);
    for (int k = tid; k < 60 * 40; k += 168) {
        int ur = k / 40, uc = k - ur * 40;
        Xs[ur * 41 + uc] = xg[(size_t)ur * Ww + uc];
    }
    const float* tg = T + (size_t)(OFFc + bu0) * Ww + (OFFc + bv0);
    float tsum = 0.f, tsq = 0.f;
    for (int k = tid; k < 40 * 20; k += 168) {
        int u = k / 20, v = k - u * 20;
        float t = tg[(size_t)u * Ww + v];
        Ts[u * 21 + v] = t;
        tsum += t; tsq = fmaf(t, t, tsq);
    }
    blockReduce2(tsum, tsq, sh);     // includes the needed __syncthreads()
    if (tid == 0) { g_tb[b] = tsum; g_tbq[b] = tsq; }

    int i = tid >> 3;                // 0..20 row lag
    int r = tid & 7;                 // reduction slice

    float acc[21];
#pragma unroll
    for (int j = 0; j < 21; j++) acc[j] = 0.f;

    for (int uu = 0; uu < 5; uu++) {         // rows r, r+8, ..., r+32
        int urow = r + uu * 8;
        const float* tsrow = Ts + urow * 21;
        const float* xsrow = Xs + (i + urow) * 41;

        float xw[40];                        // whole row window in registers
#pragma unroll
        for (int m = 0; m < 40; m++) xw[m] = xsrow[m];

#pragma unroll
        for (int dv = 0; dv < 20; dv++) {
            float t = tsrow[dv];
#pragma unroll
            for (int j = 0; j < 21; j++)
                acc[j] = fmaf(t, xw[dv + j], acc[j]);
        }
    }

#pragma unroll
    for (int j = 0; j < 21; j++) {
        float v = acc[j];
        v += __shfl_down_sync(0xffffffffu, v, 4, 8);
        v += __shfl_down_sync(0xffffffffu, v, 2, 8);
        v += __shfl_down_sync(0xffffffffu, v, 1, 8);
        if (r == 0)
            g_corr[(i * 21 + j) * ND3 + b] = v;   // lag-major for kE0
    }
}

// ---------------- E0: reduce per-lag partials (deterministic) ------------
__global__ void kE0() {
    __shared__ float sh[64];
    int lag = blockIdx.x, tid = threadIdx.x;
    float s = 0.f, dummy = 0.f;
    const float* p = g_corr + (size_t)lag * ND3;
    for (int k = tid; k < ND3; k += 128) s += p[k];
    blockReduce2(s, dummy, sh);
    if (tid == 0) g_sum[lag] = s;
}

// ---------------- E: window sums + NCC + argmax + subpixel ---------------
__global__ void __launch_bounds__(672) kE(float* __restrict__ out, int out_size) {
    __shared__ float sh[64];
    __shared__ float s_mT, s_tvar;
    __shared__ float s_ls[441], s_lq[441];
    __shared__ float s_ncc[441];
    __shared__ float rv[512];
    __shared__ int   ridx[512];
    int tid  = threadIdx.x;
    int wid  = tid >> 5;
    int lane = tid & 31;

    // --- phase 1: template stats from kD's per-block partials ---
    float s = 0.f, q = 0.f;
    for (int k = tid; k < ND3; k += 672) { s += g_tb[k]; q += g_tbq[k]; }
    blockReduce2(s, q, sh);
    if (tid == 0) {
        float N = (float)TWc * (float)TWc;
        float mT = s / N;
        s_mT = mT;
        s_tvar = q - N * mT * mT + EPSc;
    }

    // --- phase 2: per-row-lag window sums ---
    if (wid < 21) {
        int i = wid;
        const float* px = g_colx + i * 900;
        const float* pq = g_colq + i * 900;
        float ts = 0.f, tq = 0.f;
        for (int c = lane; c < 900; c += 32) { ts += px[c]; tq += pq[c]; }
        for (int o = 16; o > 0; o >>= 1) {
            ts += __shfl_down_sync(0xffffffffu, ts, o);
            tq += __shfl_down_sync(0xffffffffu, tq, o);
        }
        float tot  = __shfl_sync(0xffffffffu, ts, 0);
        float totq = __shfl_sync(0xffffffffu, tq, 0);
        if (lane < 21) {
            int j = lane;
            float hp = 0.f, hq = 0.f, tl = 0.f, tlq = 0.f;
            for (int k = 0; k < j; k++)  { hp += px[k];       hq += pq[k]; }
            for (int k = j; k < 20; k++) { tl += px[880 + k]; tlq += pq[880 + k]; }
            s_ls[i * 21 + j] = tot  - hp - tl;
            s_lq[i * 21 + j] = totq - hq - tlq;
        }
    }
    __syncthreads();

    // --- phase 3: NCC ---
    float mT = s_mT, tvar = s_tvar;
    if (tid < 441) {
        float corr = g_sum[tid];
        float ls   = s_ls[tid];
        float num  = corr - mT * ls;
        float var  = s_lq[tid] - ls * ls * (1.0f / ((float)TWc * (float)TWc)) + EPSc;
        var = fmaxf(var, 0.f);
        float ncc = num / sqrtf(tvar * var);
        if (isnan(ncc)) ncc = 0.f;
        s_ncc[tid] = ncc;
    }
    if (tid < 512) {
        rv[tid]   = -FLT_MAX;
        ridx[tid] = (1 << 20);
    }
    __syncthreads();
    if (tid < 441) { rv[tid] = s_ncc[tid]; ridx[tid] = tid; }
    __syncthreads();

    // --- phase 4: argmax (first-index tie-break) ---
    for (int off = 256; off > 0; off >>= 1) {
        if (tid < off) {
            float v2 = rv[tid + off]; int i2 = ridx[tid + off];
            if (v2 > rv[tid] || (v2 == rv[tid] && i2 < ridx[tid])) {
                rv[tid] = v2; ridx[tid] = i2;
            }
        }
        __syncthreads();
    }

    if (tid == 0) {
        int idx = ridx[0];
        int sx = idx / Sc, sy = idx % Sc;
        auto at = [&](int r, int c) {
            r = r < 0 ? 0 : (r > Sc - 1 ? Sc - 1 : r);
            c = c < 0 ? 0 : (c > Sc - 1 ? Sc - 1 : c);
            return logf(s_ncc[r * Sc + c]);
        };
        float l4  = 4.f * at(sx, sy);
        float lxm = at(sx - 1, sy), lxp = at(sx + 1, sy);
        float lym = at(sx, sy - 1), lyp = at(sx, sy + 1);
        float xs = -((float)sx - (float)MSc) - (lxm - lxp) / (2.f * lxm - l4 + 2.f * lxp);
        float ys = -((float)sy - (float)MSc) - (lym - lyp) / (2.f * lym - l4 + 2.f * lyp);
        g_xy[0] = xs; g_xy[1] = ys;
        if (out_size >= Hh * Ww + 2) {
            out[Hh * Ww]     = xs;
            out[Hh * Ww + 1] = ys;
        }
    }
}

// ---------------- F: bilinear shift + transposed store ----------------
__global__ void kF(const float* __restrict__ X, float* __restrict__ out) {
    __shared__ float tile[32][33];
    float xs = g_xy[0], ys = g_xy[1];
    int tx = threadIdx.x, ty = threadIdx.y;
    int r = blockIdx.y * 32 + ty;
    int c = blockIdx.x * 32 + tx;

    float rr = (float)r - xs, cc = (float)c - ys;
    float r0f = floorf(rr), c0f = floorf(cc);
    float wr = rr - r0f, wc = cc - c0f;
    int r0 = (int)r0f, c0 = (int)c0f;

    bool rv0 = (r0 >= 0 && r0 < Hh), rv1 = (r0 + 1 >= 0 && r0 + 1 < Hh);
    bool cv0 = (c0 >= 0 && c0 < Ww), cv1 = (c0 + 1 >= 0 && c0 + 1 < Ww);
    float v00 = 0.f, v01 = 0.f, v10 = 0.f, v11 = 0.f;
    if (rv0 && cv0) v00 = X[(size_t)r0 * Ww + c0];
    if (rv0 && cv1) v01 = X[(size_t)r0 * Ww + c0 + 1];
    if (rv1 && cv0) v10 = X[(size_t)(r0 + 1) * Ww + c0];
    if (rv1 && cv1) v11 = X[(size_t)(r0 + 1) * Ww + c0 + 1];

    float val = (1.f - wr) * (1.f - wc) * v00 + (1.f - wr) * wc * v01
              + wr * (1.f - wc) * v10 + wr * wc * v11;
    tile[ty][tx] = val;
    __syncthreads();

    out[(size_t)(blockIdx.x * 32 + ty) * Hh + (blockIdx.y * 32 + tx)] = tile[tx][ty];
}

// ---------------- launch: single stream, linear graph ----------------
extern "C" void kernel_launch(void* const* d_in, const int* in_sizes, int n_in,
                              void* d_out, int out_size) {
    const float* X    = (const float*)d_in[0];  // (1,1024,1024,1)
    const float* tmpl = (const float*)d_in[1];  // (1024,1024)
    float* out = (float*)d_out;

    dim3 gB1(8, 20);
    dim3 gF(32, 32), bF(32, 32);

    kB1<<<gB1, 128>>>(X);
    kB2<<<4, 256>>>(X);
    kD<<<ND3, 168>>>(X, tmpl);
    kE0<<<441, 128>>>();
    kE<<<1, 672>>>(out, out_size);
    kF<<<gF, bF>>>(X, out);
}

// round 12
// speedup vs baseline: 1.2251x; 1.2251x over previous
#include <cuda_runtime.h>
#include <math.h>
#include <float.h>

#define Hh   1024
#define Ww   1024
#define CSc  62      // (1024-900)/2
#define OFFc 72      // MS + CS
#define TWc  880     // template window
#define Sc   21      // 2*MS+1
#define MSc  10
#define EPSc 1e-8f

#define ND2 484      // kernel D blocks (22 x 22 tiles of 40x40)

// ---------------- scratch (no allocation allowed) ----------------
__device__ float g_tb[ND2], g_tbq[ND2];       // per-block template sum / sumsq
__device__ float g_part[20 * 900];            // 45-row chunk partial sums
__device__ float g_partq[20 * 900];
__device__ float g_colx[21 * 900];            // column sliding sums of Xc
__device__ float g_colq[21 * 900];
__device__ float g_corr[441 * ND2];           // lag-major correlation partials
__device__ float g_ncc[441];                  // final NCC surface
__device__ float g_xy[2];                     // xs, ys

// ---------------- helpers ----------------
__device__ __forceinline__ void blockReduce2(float& s, float& q, float* sh) {
    int lane = threadIdx.x & 31, w = threadIdx.x >> 5;
    for (int o = 16; o > 0; o >>= 1) {
        s += __shfl_down_sync(0xffffffffu, s, o);
        q += __shfl_down_sync(0xffffffffu, q, o);
    }
    if (lane == 0) { sh[w] = s; sh[32 + w] = q; }
    __syncthreads();
    int nw = (blockDim.x + 31) >> 5;
    if (w == 0) {
        s = (lane < nw) ? sh[lane] : 0.f;
        q = (lane < nw) ? sh[32 + lane] : 0.f;
        for (int o = 16; o > 0; o >>= 1) {
            s += __shfl_down_sync(0xffffffffu, s, o);
            q += __shfl_down_sync(0xffffffffu, q, o);
        }
    }
    __syncthreads();
}

// ---------------- B1: per-column 45-row chunk partial sums ---------------
__global__ void kB1(const float* __restrict__ X) {
    int c = blockIdx.x * 128 + threadIdx.x;
    if (c >= 900) return;
    int r0 = blockIdx.y * 45;
    const float* p = X + (size_t)(CSc + r0) * Ww + CSc + c;
    float s = 0.f, q = 0.f;
#pragma unroll 5
    for (int r = 0; r < 45; r++) { float v = p[(size_t)r * Ww]; s += v; q = fmaf(v, v, q); }
    g_part[blockIdx.y * 900 + c] = s;
    g_partq[blockIdx.y * 900 + c] = q;
}

// ---------------- B2: total - head - tail  -> 21 sliding column sums -----
__global__ void kB2(const float* __restrict__ X) {
    int c = blockIdx.x * 256 + threadIdx.x;
    if (c >= 900) return;
    float s = 0.f, q = 0.f;
#pragma unroll
    for (int k = 0; k < 20; k++) { s += g_part[k * 900 + c]; q += g_partq[k * 900 + c]; }
    const float* p = X + (size_t)CSc * Ww + CSc + c;
    float ts = 0.f, tq = 0.f;
#pragma unroll
    for (int k = 0; k < 20; k++) {
        float w = p[(size_t)(880 + k) * Ww]; ts += w; tq = fmaf(w, w, tq);
    }
    float hp = 0.f, hq = 0.f;
#pragma unroll
    for (int i = 0; i < 21; i++) {
        g_colx[i * 900 + c] = s - hp - ts;
        g_colq[i * 900 + c] = q - hq - tq;
        if (i < 20) {
            float v = p[(size_t)i * Ww];          hp += v; hq = fmaf(v, v, hq);
            float w = p[(size_t)(880 + i) * Ww];  ts -= w; tq -= w * w;
        }
    }
}

// ---------------- D: correlation, 40x40 tiles (R10 measured-best) --------
// 168 threads = 21 row-lags x 8 reduction slices. Also computes per-block
// template sum/sumsq during the Ts load (replaces old kA).
__global__ void __launch_bounds__(168, 3) kD(const float* __restrict__ X,
                                             const float* __restrict__ T) {
    __shared__ float Xs[60 * 65];    // pitch 65: conflict-free
    __shared__ float Ts[40 * 41];    // pitch 41: conflict-free
    __shared__ float sh[64];
    int b = blockIdx.x;
    int bi = b / 22, bj = b % 22;    // 22 x 22 tiles of 40 x 40
    int bu0 = bi * 40, bv0 = bj * 40;
    int tid = threadIdx.x;

    const float* xg = X + (size_t)(CSc + bu0) * Ww + (CSc + bv0);
    for (int k = tid; k < 60 * 60; k += 168) {
        int ur = k / 60, uc = k - ur * 60;
        Xs[ur * 65 + uc] = xg[(size_t)ur * Ww + uc];
    }
    const float* tg = T + (size_t)(OFFc + bu0) * Ww + (OFFc + bv0);
    float tsum = 0.f, tsq = 0.f;
    for (int k = tid; k < 40 * 40; k += 168) {
        int u = k / 40, v = k - u * 40;
        float t = tg[(size_t)u * Ww + v];
        Ts[u * 41 + v] = t;
        tsum += t; tsq = fmaf(t, t, tsq);
    }
    blockReduce2(tsum, tsq, sh);     // first __syncthreads also fences Xs/Ts
    if (tid == 0) { g_tb[b] = tsum; g_tbq[b] = tsq; }

    int i = tid >> 3;                // 0..20 row lag
    int r = tid & 7;                 // reduction slice

    float acc[21];
#pragma unroll
    for (int j = 0; j < 21; j++) acc[j] = 0.f;

    for (int uu = 0; uu < 5; uu++) {         // rows r, r+8, ..., r+32
        int urow = r + uu * 8;
        const float* tsrow = Ts + urow * 41;
        const float* xsrow = Xs + (i + urow) * 65;

        float xw[60];
#pragma unroll
        for (int m = 0; m < 60; m++) xw[m] = xsrow[m];

#pragma unroll
        for (int dv = 0; dv < 40; dv++) {
            float t = tsrow[dv];
#pragma unroll
            for (int j = 0; j < 21; j++)
                acc[j] = fmaf(t, xw[dv + j], acc[j]);
        }
    }

#pragma unroll
    for (int j = 0; j < 21; j++) {
        float v = acc[j];
        v += __shfl_down_sync(0xffffffffu, v, 4, 8);
        v += __shfl_down_sync(0xffffffffu, v, 2, 8);
        v += __shfl_down_sync(0xffffffffu, v, 1, 8);
        if (r == 0)
            g_corr[(i * 21 + j) * ND2 + b] = v;   // lag-major, float4-aligned
    }
}

// ---------------- N: per-lag final NCC (441 blocks x 256 threads) --------
// Each block: reduce 484 corr partials + 484x2 template partials (float4),
// its colx/colq row (225 float4 x2), head/tail windows -> ncc[lag].
__global__ void __launch_bounds__(256) kN() {
    __shared__ float sh[64];
    __shared__ float red[6];
    int lag = blockIdx.x;
    int i = lag / 21, j = lag % 21;
    int tid = threadIdx.x;

    // corr partial sum (121 float4)
    float cs = 0.f;
    {
        const float4* p = (const float4*)(g_corr + (size_t)lag * ND2);
        if (tid < 121) { float4 v = p[tid]; cs = v.x + v.y + v.z + v.w; }
    }
    // template stats (121 float4 each)
    float ts = 0.f, tq = 0.f;
    if (tid >= 128 && tid < 249) {
        const float4* pa = (const float4*)g_tb;
        const float4* pb = (const float4*)g_tbq;
        float4 a = pa[tid - 128], c = pb[tid - 128];
        ts = a.x + a.y + a.z + a.w;
        tq = c.x + c.y + c.z + c.w;
    }
    // colx/colq row totals (225 float4 each): all 256 threads, strided
    float ls = 0.f, lq = 0.f;
    {
        const float4* px = (const float4*)(g_colx + i * 900);
        const float4* pq = (const float4*)(g_colq + i * 900);
        if (tid < 225) { float4 v = px[tid]; ls = v.x + v.y + v.z + v.w;
                         float4 w = pq[tid]; lq = w.x + w.y + w.z + w.w; }
    }
    // head/tail correction partials (threads 0..19 contribute negatives)
    float hc = 0.f, hcq = 0.f;
    if (tid < 20) {
        const float* px = g_colx + i * 900;
        const float* pq = g_colq + i * 900;
        if (tid < j)  { hc -= px[tid];       hcq -= pq[tid]; }
        if (tid >= j) { hc -= px[880 + tid]; hcq -= pq[880 + tid]; }
    }

    // three paired reductions
    float a1 = cs, a2 = ts;
    blockReduce2(a1, a2, sh);
    if (tid == 0) { red[0] = a1; red[1] = a2; }
    float b1 = tq, b2 = ls;
    blockReduce2(b1, b2, sh);
    if (tid == 0) { red[2] = b1; red[3] = b2; }
    float c1 = lq, c2 = hc + hcq;  // keep hc/hcq separate below instead
    c2 = hc;
    float c3 = hcq;
    blockReduce2(c1, c2, sh);
    if (tid == 0) { red[4] = c1; red[5] = c2; }
    float d1 = c3, d2 = 0.f;
    blockReduce2(d1, d2, sh);

    if (tid == 0) {
        float corr = red[0];
        float tsum = red[1], tsq = red[2];
        float lsv  = red[3] + red[5];        // row total + head/tail correction
        float lqv  = red[4] + d1;
        float N = (float)TWc * (float)TWc;
        float mT = tsum / N;
        float tvar = tsq - N * mT * mT + EPSc;
        float num = corr - mT * lsv;
        float var = lqv - lsv * lsv * (1.0f / N) + EPSc;
        var = fmaxf(var, 0.f);
        float ncc = num / sqrtf(tvar * var);
        if (isnan(ncc)) ncc = 0.f;
        g_ncc[lag] = ncc;
    }
}

// ---------------- E: argmax + subpixel (tiny) ----------------------------
__global__ void __launch_bounds__(512) kE(float* __restrict__ out, int out_size) {
    __shared__ float s_ncc[441];
    __shared__ float rv[512];
    __shared__ int   ridx[512];
    int tid = threadIdx.x;

    if (tid < 441) s_ncc[tid] = g_ncc[tid];
    rv[tid]   = (tid < 441) ? g_ncc[tid] : -FLT_MAX;
    ridx[tid] = (tid < 441) ? tid : (1 << 20);
    __syncthreads();

    for (int off = 256; off > 0; off >>= 1) {
        if (tid < off) {
            float v2 = rv[tid + off]; int i2 = ridx[tid + off];
            if (v2 > rv[tid] || (v2 == rv[tid] && i2 < ridx[tid])) {
                rv[tid] = v2; ridx[tid] = i2;
            }
        }
        __syncthreads();
    }

    if (tid == 0) {
        int idx = ridx[0];
        int sx = idx / Sc, sy = idx % Sc;
        auto at = [&](int r, int c) {
            r = r < 0 ? 0 : (r > Sc - 1 ? Sc - 1 : r);
            c = c < 0 ? 0 : (c > Sc - 1 ? Sc - 1 : c);
            return logf(s_ncc[r * Sc + c]);
        };
        float l4  = 4.f * at(sx, sy);
        float lxm = at(sx - 1, sy), lxp = at(sx + 1, sy);
        float lym = at(sx, sy - 1), lyp = at(sx, sy + 1);
        float xs = -((float)sx - (float)MSc) - (lxm - lxp) / (2.f * lxm - l4 + 2.f * lxp);
        float ys = -((float)sy - (float)MSc) - (lym - lyp) / (2.f * lym - l4 + 2.f * lyp);
        g_xy[0] = xs; g_xy[1] = ys;
        if (out_size >= Hh * Ww + 2) {
            out[Hh * Ww]     = xs;
            out[Hh * Ww + 1] = ys;
        }
    }
}

// ---------------- F: bilinear shift + transposed store ----------------
__global__ void kF(const float* __restrict__ X, float* __restrict__ out) {
    __shared__ float tile[32][33];
    float xs = g_xy[0], ys = g_xy[1];
    int tx = threadIdx.x, ty = threadIdx.y;
    int r = blockIdx.y * 32 + ty;
    int c = blockIdx.x * 32 + tx;

    float rr = (float)r - xs, cc = (float)c - ys;
    float r0f = floorf(rr), c0f = floorf(cc);
    float wr = rr - r0f, wc = cc - c0f;
    int r0 = (int)r0f, c0 = (int)c0f;

    bool rv0 = (r0 >= 0 && r0 < Hh), rv1 = (r0 + 1 >= 0 && r0 + 1 < Hh);
    bool cv0 = (c0 >= 0 && c0 < Ww), cv1 = (c0 + 1 >= 0 && c0 + 1 < Ww);
    float v00 = 0.f, v01 = 0.f, v10 = 0.f, v11 = 0.f;
    if (rv0 && cv0) v00 = X[(size_t)r0 * Ww + c0];
    if (rv0 && cv1) v01 = X[(size_t)r0 * Ww + c0 + 1];
    if (rv1 && cv0) v10 = X[(size_t)(r0 + 1) * Ww + c0];
    if (rv1 && cv1) v11 = X[(size_t)(r0 + 1) * Ww + c0 + 1];

    float val = (1.f - wr) * (1.f - wc) * v00 + (1.f - wr) * wc * v01
              + wr * (1.f - wc) * v10 + wr * wc * v11;
    tile[ty][tx] = val;
    __syncthreads();

    out[(size_t)(blockIdx.x * 32 + ty) * Hh + (blockIdx.y * 32 + tx)] = tile[tx][ty];
}

// ---------------- launch: single stream, linear graph ----------------
extern "C" void kernel_launch(void* const* d_in, const int* in_sizes, int n_in,
                              void* d_out, int out_size) {
    const float* X    = (const float*)d_in[0];  // (1,1024,1024,1)
    const float* tmpl = (const float*)d_in[1];  // (1024,1024)
    float* out = (float*)d_out;

    dim3 gB1(8, 20);
    dim3 gF(32, 32), bF(32, 32);

    kB1<<<gB1, 128>>>(X);
    kB2<<<4, 256>>>(X);
    kD<<<ND2, 168>>>(X, tmpl);
    kN<<<441, 256>>>();
    kE<<<1, 512>>>(out, out_size);
    kF<<<gF, bF>>>(X, out);
}

// round 13
// speedup vs baseline: 1.2776x; 1.0429x over previous
#include <cuda_runtime.h>
#include <math.h>
#include <float.h>

#define Hh   1024
#define Ww   1024
#define CSc  62      // (1024-900)/2
#define OFFc 72      // MS + CS
#define TWc  880     // template window
#define Sc   21      // 2*MS+1
#define MSc  10
#define EPSc 1e-8f

#define ND2 484      // kernel D blocks (22 x 22 tiles of 40x40)
#define NBI 22       // row-tile groups (bi)
#define CP  24       // padded slots per lag (22 used, float4-aligned)

// ---------------- scratch (no allocation allowed) ----------------
__device__ float g_tb[ND2], g_tbq[ND2];       // per-block template sum / sumsq
__device__ float g_part[20 * 900];            // 45-row chunk partial sums
__device__ float g_partq[20 * 900];
__device__ float g_colx[21 * 900];            // column sliding sums of Xc
__device__ float g_colq[21 * 900];
__device__ __align__(16) float g_corr2[441 * CP];  // per-(lag, bi) partials
__device__ float g_xy[2];                     // xs, ys

// ---------------- helpers ----------------
__device__ __forceinline__ void blockReduce2(float& s, float& q, float* sh) {
    int lane = threadIdx.x & 31, w = threadIdx.x >> 5;
    for (int o = 16; o > 0; o >>= 1) {
        s += __shfl_down_sync(0xffffffffu, s, o);
        q += __shfl_down_sync(0xffffffffu, q, o);
    }
    if (lane == 0) { sh[w] = s; sh[32 + w] = q; }
    __syncthreads();
    int nw = (blockDim.x + 31) >> 5;
    if (w == 0) {
        s = (lane < nw) ? sh[lane] : 0.f;
        q = (lane < nw) ? sh[32 + lane] : 0.f;
        for (int o = 16; o > 0; o >>= 1) {
            s += __shfl_down_sync(0xffffffffu, s, o);
            q += __shfl_down_sync(0xffffffffu, q, o);
        }
    }
    __syncthreads();
}

// ---------------- B1: per-column 45-row chunk partial sums ---------------
__global__ void kB1(const float* __restrict__ X) {
    int c = blockIdx.x * 128 + threadIdx.x;
    if (c >= 900) return;
    int r0 = blockIdx.y * 45;
    const float* p = X + (size_t)(CSc + r0) * Ww + CSc + c;
    float s = 0.f, q = 0.f;
#pragma unroll 5
    for (int r = 0; r < 45; r++) { float v = p[(size_t)r * Ww]; s += v; q = fmaf(v, v, q); }
    g_part[blockIdx.y * 900 + c] = s;
    g_partq[blockIdx.y * 900 + c] = q;
}

// ---------------- B2: sliding column sums + zero corr accumulator --------
__global__ void kB2(const float* __restrict__ X) {
    int t = blockIdx.x * 256 + threadIdx.x;   // 0..1023
    // zero g_corr2 (441*24 = 10584 floats) before kD's atomics
    for (int k = t; k < 441 * CP; k += 1024) g_corr2[k] = 0.f;

    int c = t;
    if (c >= 900) return;
    float s = 0.f, q = 0.f;
#pragma unroll
    for (int k = 0; k < 20; k++) { s += g_part[k * 900 + c]; q += g_partq[k * 900 + c]; }
    const float* p = X + (size_t)CSc * Ww + CSc + c;
    float ts = 0.f, tq = 0.f;
#pragma unroll
    for (int k = 0; k < 20; k++) {
        float w = p[(size_t)(880 + k) * Ww]; ts += w; tq = fmaf(w, w, tq);
    }
    float hp = 0.f, hq = 0.f;
#pragma unroll
    for (int i = 0; i < 21; i++) {
        g_colx[i * 900 + c] = s - hp - ts;
        g_colq[i * 900 + c] = q - hq - tq;
        if (i < 20) {
            float v = p[(size_t)i * Ww];          hp += v; hq = fmaf(v, v, hq);
            float w = p[(size_t)(880 + i) * Ww];  ts -= w; tq -= w * w;
        }
    }
}

// ---------------- D: correlation, 40x40 tiles + bi-aggregated epilogue ---
__global__ void __launch_bounds__(168, 3) kD(const float* __restrict__ X,
                                             const float* __restrict__ T) {
    __shared__ float Xs[60 * 65];    // pitch 65: conflict-free
    __shared__ float Ts[40 * 41];    // pitch 41: conflict-free
    __shared__ float sh[64];
    int b = blockIdx.x;
    int bi = b / 22, bj = b % 22;    // 22 x 22 tiles of 40 x 40
    int bu0 = bi * 40, bv0 = bj * 40;
    int tid = threadIdx.x;

    const float* xg = X + (size_t)(CSc + bu0) * Ww + (CSc + bv0);
    for (int k = tid; k < 60 * 60; k += 168) {
        int ur = k / 60, uc = k - ur * 60;
        Xs[ur * 65 + uc] = xg[(size_t)ur * Ww + uc];
    }
    const float* tg = T + (size_t)(OFFc + bu0) * Ww + (OFFc + bv0);
    float tsum = 0.f, tsq = 0.f;
    for (int k = tid; k < 40 * 40; k += 168) {
        int u = k / 40, v = k - u * 40;
        float t = tg[(size_t)u * Ww + v];
        Ts[u * 41 + v] = t;
        tsum += t; tsq = fmaf(t, t, tsq);
    }
    blockReduce2(tsum, tsq, sh);     // first __syncthreads also fences Xs/Ts
    if (tid == 0) { g_tb[b] = tsum; g_tbq[b] = tsq; }

    int i = tid >> 3;                // 0..20 row lag
    int r = tid & 7;                 // reduction slice

    float acc[21];
#pragma unroll
    for (int j = 0; j < 21; j++) acc[j] = 0.f;

    for (int uu = 0; uu < 5; uu++) {         // rows r, r+8, ..., r+32
        int urow = r + uu * 8;
        const float* tsrow = Ts + urow * 41;
        const float* xsrow = Xs + (i + urow) * 65;

        float xw[60];
#pragma unroll
        for (int m = 0; m < 60; m++) xw[m] = xsrow[m];

#pragma unroll
        for (int dv = 0; dv < 40; dv++) {
            float t = tsrow[dv];
#pragma unroll
            for (int j = 0; j < 21; j++)
                acc[j] = fmaf(t, xw[dv + j], acc[j]);
        }
    }

#pragma unroll
    for (int j = 0; j < 21; j++) {
        float v = acc[j];
        v += __shfl_down_sync(0xffffffffu, v, 4, 8);
        v += __shfl_down_sync(0xffffffffu, v, 2, 8);
        v += __shfl_down_sync(0xffffffffu, v, 1, 8);
        if (r == 0)
            atomicAdd(&g_corr2[(i * 21 + j) * CP + bi], v);  // 22-way spread
    }
}

// ---------------- E: all reductions + NCC + argmax + subpixel ------------
__global__ void __launch_bounds__(672) kE(float* __restrict__ out, int out_size) {
    __shared__ float sh[64];
    __shared__ float s_mT, s_tvar;
    __shared__ float s_ls[441], s_lq[441];
    __shared__ float s_ncc[441];
    __shared__ float rv[512];
    __shared__ int   ridx[512];
    int tid  = threadIdx.x;
    int wid  = tid >> 5;
    int lane = tid & 31;

    // --- phase A: template stats from kD's per-block partials (484) ---
    float s = 0.f, q = 0.f;
    if (tid < ND2) { s = g_tb[tid]; q = g_tbq[tid]; }
    blockReduce2(s, q, sh);
    if (tid == 0) {
        float N = (float)TWc * (float)TWc;
        float mT = s / N;
        s_mT = mT;
        s_tvar = q - N * mT * mT + EPSc;
    }

    // --- phase B: per-row-lag window sums (21 warps) ---
    if (wid < 21) {
        int i = wid;
        const float* px = g_colx + i * 900;
        const float* pq = g_colq + i * 900;
        float ts = 0.f, tq = 0.f;
        for (int c = lane; c < 900; c += 32) { ts += px[c]; tq += pq[c]; }
        for (int o = 16; o > 0; o >>= 1) {
            ts += __shfl_down_sync(0xffffffffu, ts, o);
            tq += __shfl_down_sync(0xffffffffu, tq, o);
        }
        float tot  = __shfl_sync(0xffffffffu, ts, 0);
        float totq = __shfl_sync(0xffffffffu, tq, 0);
        if (lane < 21) {
            int j = lane;
            float hp = 0.f, hq = 0.f, tl = 0.f, tlq = 0.f;
            for (int k = 0; k < j; k++)  { hp += px[k];       hq += pq[k]; }
            for (int k = j; k < 20; k++) { tl += px[880 + k]; tlq += pq[880 + k]; }
            s_ls[i * 21 + j] = tot  - hp - tl;
            s_lq[i * 21 + j] = totq - hq - tlq;
        }
    }
    __syncthreads();

    // --- phase C: corr finalize + NCC ---
    float mT = s_mT, tvar = s_tvar;
    if (tid < 441) {
        const float4* p = (const float4*)(g_corr2 + tid * CP);
        float corr = 0.f;
#pragma unroll
        for (int k = 0; k < 6; k++) {
            float4 v = p[k];
            corr += (v.x + v.y) + (v.z + v.w);   // slots 22,23 are zero
        }
        float ls  = s_ls[tid];
        float num = corr - mT * ls;
        float var = s_lq[tid] - ls * ls * (1.0f / ((float)TWc * (float)TWc)) + EPSc;
        var = fmaxf(var, 0.f);
        float ncc = num / sqrtf(tvar * var);
        if (isnan(ncc)) ncc = 0.f;
        s_ncc[tid] = ncc;
    }
    if (tid < 512) { rv[tid] = -FLT_MAX; ridx[tid] = (1 << 20); }
    __syncthreads();
    if (tid < 441) { rv[tid] = s_ncc[tid]; ridx[tid] = tid; }
    __syncthreads();

    // --- phase D: argmax (first-index tie-break) ---
    for (int off = 256; off > 0; off >>= 1) {
        if (tid < off) {
            float v2 = rv[tid + off]; int i2 = ridx[tid + off];
            if (v2 > rv[tid] || (v2 == rv[tid] && i2 < ridx[tid])) {
                rv[tid] = v2; ridx[tid] = i2;
            }
        }
        __syncthreads();
    }

    if (tid == 0) {
        int idx = ridx[0];
        int sx = idx / Sc, sy = idx % Sc;
        auto at = [&](int r, int c) {
            r = r < 0 ? 0 : (r > Sc - 1 ? Sc - 1 : r);
            c = c < 0 ? 0 : (c > Sc - 1 ? Sc - 1 : c);
            return logf(s_ncc[r * Sc + c]);
        };
        float l4  = 4.f * at(sx, sy);
        float lxm = at(sx - 1, sy), lxp = at(sx + 1, sy);
        float lym = at(sx, sy - 1), lyp = at(sx, sy + 1);
        float xs = -((float)sx - (float)MSc) - (lxm - lxp) / (2.f * lxm - l4 + 2.f * lxp);
        float ys = -((float)sy - (float)MSc) - (lym - lyp) / (2.f * lym - l4 + 2.f * lyp);
        g_xy[0] = xs; g_xy[1] = ys;
        if (out_size >= Hh * Ww + 2) {
            out[Hh * Ww]     = xs;
            out[Hh * Ww + 1] = ys;
        }
    }
}

// ---------------- F: bilinear shift + transposed store ----------------
__global__ void kF(const float* __restrict__ X, float* __restrict__ out) {
    __shared__ float tile[32][33];
    float xs = g_xy[0], ys = g_xy[1];
    int tx = threadIdx.x, ty = threadIdx.y;
    int r = blockIdx.y * 32 + ty;
    int c = blockIdx.x * 32 + tx;

    float rr = (float)r - xs, cc = (float)c - ys;
    float r0f = floorf(rr), c0f = floorf(cc);
    float wr = rr - r0f, wc = cc - c0f;
    int r0 = (int)r0f, c0 = (int)c0f;

    bool rv0 = (r0 >= 0 && r0 < Hh), rv1 = (r0 + 1 >= 0 && r0 + 1 < Hh);
    bool cv0 = (c0 >= 0 && c0 < Ww), cv1 = (c0 + 1 >= 0 && c0 + 1 < Ww);
    float v00 = 0.f, v01 = 0.f, v10 = 0.f, v11 = 0.f;
    if (rv0 && cv0) v00 = X[(size_t)r0 * Ww + c0];
    if (rv0 && cv1) v01 = X[(size_t)r0 * Ww + c0 + 1];
    if (rv1 && cv0) v10 = X[(size_t)(r0 + 1) * Ww + c0];
    if (rv1 && cv1) v11 = X[(size_t)(r0 + 1) * Ww + c0 + 1];

    float val = (1.f - wr) * (1.f - wc) * v00 + (1.f - wr) * wc * v01
              + wr * (1.f - wc) * v10 + wr * wc * v11;
    tile[ty][tx] = val;
    __syncthreads();

    out[(size_t)(blockIdx.x * 32 + ty) * Hh + (blockIdx.y * 32 + tx)] = tile[tx][ty];
}

// ---------------- launch: single stream, linear graph, 5 nodes -----------
extern "C" void kernel_launch(void* const* d_in, const int* in_sizes, int n_in,
                              void* d_out, int out_size) {
    const float* X    = (const float*)d_in[0];  // (1,1024,1024,1)
    const float* tmpl = (const float*)d_in[1];  // (1024,1024)
    float* out = (float*)d_out;

    dim3 gB1(8, 20);
    dim3 gF(32, 32), bF(32, 32);

    kB1<<<gB1, 128>>>(X);
    kB2<<<4, 256>>>(X);
    kD<<<ND2, 168>>>(X, tmpl);
    kE<<<1, 672>>>(out, out_size);
    kF<<<gF, bF>>>(X, out);
}